// round 13
// baseline (speedup 1.0000x reference)
#include <cuda_runtime.h>
#include <cstdint>
#include <math.h>

#define H        4096
#define HD       128
#define NKV      8
#define NREP     4
#define MAXB     128
#define MAXL     1024
#define SCP      (MAXL + 4)

// ---------------- scratch (no allocations allowed) ----------------
__device__ float g_xn[MAXB * H];
__device__ float g_q[MAXB * H];
__device__ float g_vnew[MAXB * NKV * HD];
__device__ float g_att[MAXB * H];
__device__ float g_rope[HD];
__device__ int   g_ticket;

__device__ __forceinline__ uint32_t f2tf(float f) {
    uint32_t u; asm("cvt.rna.tf32.f32 %0, %1;" : "=r"(u) : "f"(f)); return u;
}
__device__ __forceinline__ float tf32r(float f) {
    return __uint_as_float(f2tf(f));
}

#define DUAL_GRID 296

// ---------------- prep: zero scratch, compute rope, reset ticket ----------
__global__ void prep_kernel(int BH, int BGD, int L) {
    int i = blockIdx.x * 256 + threadIdx.x;
    if (i < BH)            g_q[i] = 0.f;
    else if (i < BH + BGD) g_vnew[i - BH] = 0.f;
    if (i == 0) g_ticket = DUAL_GRID;
    if (blockIdx.x == 0 && threadIdx.x < HD / 2) {
        int t = threadIdx.x;
        double freq = exp(-((double)t / (double)HD) * 13.122363377404329); // ln(5e5)
        double ang  = (double)L * freq;
        double cv = cos(ang), sv = sin(ang);
        g_rope[t]          = (float)(cv - sv);
        g_rope[t + HD / 2] = (float)(cv + sv);
    }
}

__global__ void zero_kernel(float* __restrict__ p, int n) {
    int i = blockIdx.x * 256 + threadIdx.x;
    if (i < n) p[i] = 0.f;
}

// ---------------- rmsnorm (writes tf32-pre-rounded xn) ----------------
__global__ void rmsnorm_kernel(const float* __restrict__ x, const float* __restrict__ w) {
    int b = blockIdx.x;
    const float* xr = x + (size_t)b * H;
    float ss = 0.f;
    for (int i = threadIdx.x; i < H; i += 256) { float v = xr[i]; ss += v * v; }
    __shared__ float red[256];
    red[threadIdx.x] = ss;
    __syncthreads();
    for (int o = 128; o > 0; o >>= 1) {
        if (threadIdx.x < o) red[threadIdx.x] += red[threadIdx.x + o];
        __syncthreads();
    }
    float inv = rsqrtf(red[0] * (1.f / H) + 1e-5f);
    for (int i = threadIdx.x; i < H; i += 256)
        g_xn[(size_t)b * H + i] = tf32r(xr[i] * inv * w[i]);
}

// ------- tf32 GEMM core: CTA 128x128, warp 64x32, LDSM A-fragments -------
__device__ __forceinline__ void cpa16(void* dst, const void* src) {
    uint32_t d = (uint32_t)__cvta_generic_to_shared(dst);
    asm volatile("cp.async.cg.shared.global [%0], [%1], 16;" :: "r"(d), "l"(src));
}
__device__ __forceinline__ void redv2(float* p, float v0, float v1) {
    asm volatile("red.global.add.v2.f32 [%0], {%1, %2};" :: "l"(p), "f"(v0), "f"(v1) : "memory");
}

#define AS_STRIDE 36
#define BS_STRIDE 136
#define ABUF (128 * AS_STRIDE)       // 4608 floats
#define BBUF (32 * BS_STRIDE)        // 4352 floats
#define SBUF (ABUF + BBUF)           // 8960 floats per stage
#define GEMM_SMEM (2 * SBUF * 4)     // 71680 bytes

// A must be tf32-pre-rounded. C accumulated via red.v2 (pre-zeroed).
__device__ __forceinline__ void gemm_core(
    const float* __restrict__ A, const float* __restrict__ B, float* __restrict__ C,
    int K, int N, int n0, int kbeg, int kchunk, float* sm)
{
    int niter = kchunk / 32;
    int tid = threadIdx.x;
    int lane = tid & 31;
    int warp = tid >> 5;
    int mb = (warp >> 2) * 64;       // 2x4 warp grid over 128x128 tile
    int nb = (warp & 3) * 32;

    // ldmatrix row-address components: lane>>3 selects (row-half, col-half)
    int lgrp = lane >> 3;            // 0..3
    int lrow = (lgrp & 1) * 8 + (lane & 7);     // row within 16-row block
    int lcol = (lgrp >> 1) * 4;                 // col offset (floats)
    uint32_t smsh = (uint32_t)__cvta_generic_to_shared(sm);

    float c[4][4][4];
    #pragma unroll
    for (int i = 0; i < 4; i++)
        #pragma unroll
        for (int j = 0; j < 4; j++)
            #pragma unroll
            for (int k = 0; k < 4; k++) c[i][j][k] = 0.f;

    auto stage = [&](int buf, int k0) {
        float* Asb = sm + buf * SBUF;
        float* Bsb = Asb + ABUF;
        #pragma unroll
        for (int j = 0; j < 4; j++) {           // A: 128x32 = 1024 float4
            int id = tid + 256 * j;
            int row = id >> 3, kq = (id & 7) * 4;
            cpa16(Asb + row * AS_STRIDE + kq, A + (size_t)row * K + k0 + kq);
        }
        #pragma unroll
        for (int j = 0; j < 4; j++) {           // B: 32x128 = 1024 float4
            int id = tid + 256 * j;
            int row = id >> 5, nq = (id & 31) * 4;
            cpa16(Bsb + row * BS_STRIDE + nq, B + (size_t)(k0 + row) * N + n0 + nq);
        }
        asm volatile("cp.async.commit_group;");
    };

    stage(0, kbeg);
    for (int i = 0; i < niter; i++) {
        if (i + 1 < niter) {
            stage((i + 1) & 1, kbeg + (i + 1) * 32);
            asm volatile("cp.async.wait_group 1;");
        } else {
            asm volatile("cp.async.wait_group 0;");
        }
        __syncthreads();

        uint32_t Ash = smsh + (uint32_t)((i & 1) * SBUF) * 4;
        float* Bsb = sm + (i & 1) * SBUF + ABUF;
        #pragma unroll
        for (int ks = 0; ks < 4; ks++) {
            int kk = ks * 8;
            uint32_t a[4][4], bf[4][2];
            #pragma unroll
            for (int im = 0; im < 4; im++) {
                // one LDSM.x4 loads the full 16x8 tf32 A fragment
                uint32_t adr = Ash + (uint32_t)((mb + im * 16 + lrow) * AS_STRIDE
                                                + kk + lcol) * 4;
                asm volatile(
                    "ldmatrix.sync.aligned.m8n8.x4.shared.b16 {%0,%1,%2,%3}, [%4];"
                    : "=r"(a[im][0]), "=r"(a[im][1]), "=r"(a[im][2]), "=r"(a[im][3])
                    : "r"(adr));
            }
            #pragma unroll
            for (int jn = 0; jn < 4; jn++) {
                int cc = nb + jn * 8 + (lane >> 2);
                bf[jn][0] = f2tf(Bsb[(kk + (lane & 3)) * BS_STRIDE + cc]);
                bf[jn][1] = f2tf(Bsb[(kk + 4 + (lane & 3)) * BS_STRIDE + cc]);
            }
            #pragma unroll
            for (int im = 0; im < 4; im++)
                #pragma unroll
                for (int jn = 0; jn < 4; jn++)
                    asm volatile(
                        "mma.sync.aligned.m16n8k8.row.col.f32.tf32.tf32.f32 "
                        "{%0,%1,%2,%3},{%4,%5,%6,%7},{%8,%9},{%0,%1,%2,%3};"
                        : "+f"(c[im][jn][0]), "+f"(c[im][jn][1]),
                          "+f"(c[im][jn][2]), "+f"(c[im][jn][3])
                        : "r"(a[im][0]), "r"(a[im][1]), "r"(a[im][2]), "r"(a[im][3]),
                          "r"(bf[jn][0]), "r"(bf[jn][1]));
        }
        __syncthreads();
    }

    #pragma unroll
    for (int im = 0; im < 4; im++) {
        int r = mb + im * 16 + (lane >> 2);
        #pragma unroll
        for (int jn = 0; jn < 4; jn++) {
            int col = n0 + nb + jn * 8 + (lane & 3) * 2;
            redv2(&C[(size_t)r * N + col],       c[im][jn][0], c[im][jn][1]);
            redv2(&C[(size_t)(r + 8) * N + col], c[im][jn][2], c[im][jn][3]);
        }
    }
    __syncthreads();   // smem must be safe before next persistent item stages
}

// persistent dual GEMM (wq + wv) with ticket work-stealing
#define DUAL_KS 16
__global__ void __launch_bounds__(256, 2) gemm_dual(
    const float* __restrict__ A,
    const float* __restrict__ B1, float* __restrict__ C1, int N1, int nb1,
    const float* __restrict__ B2, float* __restrict__ C2, int N2, int K,
    int nbTotal)
{
    extern __shared__ float sm[];
    __shared__ int s_item;
    int kchunk = K / DUAL_KS;                 // 256
    int nItems = nbTotal * DUAL_KS;           // 640
    int item = blockIdx.x;
    while (item < nItems) {
        int nb = item % nbTotal;
        int ks = item / nbTotal;
        if (nb < nb1) gemm_core(A, B1, C1, K, N1, nb * 128, ks * kchunk, kchunk, sm);
        else          gemm_core(A, B2, C2, K, N2, (nb - nb1) * 128, ks * kchunk, kchunk, sm);
        if (threadIdx.x == 0) s_item = atomicAdd(&g_ticket, 1);
        __syncthreads();
        item = s_item;
    }
}

__global__ void __launch_bounds__(256, 2) gemm_single(
    const float* __restrict__ A, const float* __restrict__ B, float* __restrict__ C,
    int N, int K)
{
    extern __shared__ float sm[];
    int kchunk = K / gridDim.y;
    gemm_core(A, B, C, K, N, blockIdx.x * 128, blockIdx.y * kchunk, kchunk, sm);
}

// ---------------- attention: persistent CTAs, warp-local softmax ----------
__global__ void __launch_bounds__(256, 4) attn_kernel(
    const float* __restrict__ Kc, const float* __restrict__ Vc, int L, int units)
{
    __shared__ float sc[NREP][SCP];
    __shared__ float pout[8][NREP][HD];
    __shared__ float wm[8][NREP], ws[8][NREP];
    __shared__ float fac[8][NREP], gsum[NREP];

    int t = threadIdx.x, lane = t & 31, w = t >> 5;
    bool hi16 = (lane & 16) != 0, hi8 = (lane & 8) != 0;
    float4 rp = *(const float4*)(g_rope + lane * 4);

    for (int bg = blockIdx.x; bg < units; bg += gridDim.x) {
        int b = bg >> 3, g = bg & 7;

        float4 q[NREP];
        #pragma unroll
        for (int r = 0; r < NREP; r++) {
            float4 qv = *(const float4*)(g_q + (size_t)b * H + (g * NREP + r) * HD + lane * 4);
            q[r].x = qv.x * rp.x * 0.08838834764831845f;
            q[r].y = qv.y * rp.y * 0.08838834764831845f;
            q[r].z = qv.z * rp.z * 0.08838834764831845f;
            q[r].w = qv.w * rp.w * 0.08838834764831845f;
        }

        const float* Kb = Kc + (size_t)bg * L * HD;
        int lbeg = w * (L >> 3);
        int lend = lbeg + (L >> 3);
        const float* kp = Kb + (size_t)lbeg * HD + lane * 4;
        float mloc = -1e30f;
        for (int l = lbeg; l < lend; l += 4, kp += 4 * HD) {
            float4 k0 = *(const float4*)kp;
            float4 k1 = *(const float4*)(kp + HD);
            float4 k2 = *(const float4*)(kp + 2 * HD);
            float4 k3 = *(const float4*)(kp + 3 * HD);

            #pragma unroll
            for (int pair = 0; pair < 2; pair++) {
                float4 ka = pair ? k2 : k0;
                float4 kb = pair ? k3 : k1;
                float p0[4], p1[4];
                #pragma unroll
                for (int r = 0; r < 4; r++) {
                    p0[r] = ka.x * q[r].x + ka.y * q[r].y + ka.z * q[r].z + ka.w * q[r].w;
                    p1[r] = kb.x * q[r].x + kb.y * q[r].y + kb.z * q[r].z + kb.w * q[r].w;
                }
                float a0 = hi16 ? p0[2] : p0[0];
                float a1 = hi16 ? p0[3] : p0[1];
                a0 += __shfl_xor_sync(0xffffffffu, hi16 ? p0[0] : p0[2], 16);
                a1 += __shfl_xor_sync(0xffffffffu, hi16 ? p0[1] : p0[3], 16);
                float c0 = hi8 ? a1 : a0;
                c0 += __shfl_xor_sync(0xffffffffu, hi8 ? a0 : a1, 8);
                c0 += __shfl_xor_sync(0xffffffffu, c0, 4);
                c0 += __shfl_xor_sync(0xffffffffu, c0, 2);
                c0 += __shfl_xor_sync(0xffffffffu, c0, 1);

                float b0 = hi16 ? p1[2] : p1[0];
                float b1 = hi16 ? p1[3] : p1[1];
                b0 += __shfl_xor_sync(0xffffffffu, hi16 ? p1[0] : p1[2], 16);
                b1 += __shfl_xor_sync(0xffffffffu, hi16 ? p1[1] : p1[3], 16);
                float c1 = hi8 ? b1 : b0;
                c1 += __shfl_xor_sync(0xffffffffu, hi8 ? b0 : b1, 8);
                c1 += __shfl_xor_sync(0xffffffffu, c1, 4);
                c1 += __shfl_xor_sync(0xffffffffu, c1, 2);
                c1 += __shfl_xor_sync(0xffffffffu, c1, 1);

                mloc = fmaxf(mloc, fmaxf(c0, c1));
                if ((lane & 7) == 0) {
                    int r = lane >> 3;
                    sc[r][l + pair * 2]     = c0;
                    sc[r][l + pair * 2 + 1] = c1;
                }
            }
        }
        __syncwarp();

        int r0i = lane >> 3, cix = lane & 7;
        float s_w = 0.f;
        int pcnt = L >> 6;
        for (int j = 0; j < pcnt; j++) {
            int l = lbeg + cix + j * 8;
            float p = __expf(sc[r0i][l] - mloc);
            sc[r0i][l] = p;
            s_w += p;
        }
        s_w += __shfl_xor_sync(0xffffffffu, s_w, 4);
        s_w += __shfl_xor_sync(0xffffffffu, s_w, 2);
        s_w += __shfl_xor_sync(0xffffffffu, s_w, 1);
        __syncwarp();

        const float* Vb = Vc + (size_t)bg * L * HD;
        const float* vp = Vb + (size_t)lbeg * HD + lane * 4;
        float4 o0 = {0,0,0,0}, o1 = o0, o2 = o0, o3 = o0;
        for (int l = lbeg; l < lend; l += 4, vp += 4 * HD) {
            float4 v0 = *(const float4*)vp;
            float4 v1 = *(const float4*)(vp + HD);
            float4 v2 = *(const float4*)(vp + 2 * HD);
            float4 v3 = *(const float4*)(vp + 3 * HD);
            float4 pa = *(const float4*)&sc[0][l];
            float4 pb = *(const float4*)&sc[1][l];
            float4 pc = *(const float4*)&sc[2][l];
            float4 pd = *(const float4*)&sc[3][l];
            o0.x += pa.x*v0.x + pa.y*v1.x + pa.z*v2.x + pa.w*v3.x;
            o0.y += pa.x*v0.y + pa.y*v1.y + pa.z*v2.y + pa.w*v3.y;
            o0.z += pa.x*v0.z + pa.y*v1.z + pa.z*v2.z + pa.w*v3.z;
            o0.w += pa.x*v0.w + pa.y*v1.w + pa.z*v2.w + pa.w*v3.w;
            o1.x += pb.x*v0.x + pb.y*v1.x + pb.z*v2.x + pb.w*v3.x;
            o1.y += pb.x*v0.y + pb.y*v1.y + pb.z*v2.y + pb.w*v3.y;
            o1.z += pb.x*v0.z + pb.y*v1.z + pb.z*v2.z + pb.w*v3.z;
            o1.w += pb.x*v0.w + pb.y*v1.w + pb.z*v2.w + pb.w*v3.w;
            o2.x += pc.x*v0.x + pc.y*v1.x + pc.z*v2.x + pc.w*v3.x;
            o2.y += pc.x*v0.y + pc.y*v1.y + pc.z*v2.y + pc.w*v3.y;
            o2.z += pc.x*v0.z + pc.y*v1.z + pc.z*v2.z + pc.w*v3.z;
            o2.w += pc.x*v0.w + pc.y*v1.w + pc.z*v2.w + pc.w*v3.w;
            o3.x += pd.x*v0.x + pd.y*v1.x + pd.z*v2.x + pd.w*v3.x;
            o3.y += pd.x*v0.y + pd.y*v1.y + pd.z*v2.y + pd.w*v3.y;
            o3.z += pd.x*v0.z + pd.y*v1.z + pd.z*v2.z + pd.w*v3.z;
            o3.w += pd.x*v0.w + pd.y*v1.w + pd.z*v2.w + pd.w*v3.w;
        }
        ((float4*)&pout[w][0][0])[lane] = o0;
        ((float4*)&pout[w][1][0])[lane] = o1;
        ((float4*)&pout[w][2][0])[lane] = o2;
        ((float4*)&pout[w][3][0])[lane] = o3;
        if ((lane & 7) == 0) {
            wm[w][r0i] = mloc;
            ws[w][r0i] = s_w;
        }
        __syncthreads();

        if (t < NREP) {
            float mg = -1e30f;
            #pragma unroll
            for (int ww = 0; ww < 8; ww++) mg = fmaxf(mg, wm[ww][t]);
            float sg = 0.f;
            #pragma unroll
            for (int ww = 0; ww < 8; ww++) {
                float f = __expf(wm[ww][t] - mg);
                fac[ww][t] = f;
                sg += ws[ww][t] * f;
            }
            gsum[t] = sg;
        }
        __syncthreads();

        // reduce, normalize, add v_new; store tf32-pre-rounded for wo GEMM
        for (int i = t; i < NREP * HD; i += 256) {
            int rr = i >> 7, d = i & (HD - 1);
            float acc = 0.f;
            #pragma unroll
            for (int gg = 0; gg < 8; gg++) acc += pout[gg][rr][d] * fac[gg][rr];
            acc = acc / gsum[rr] + g_vnew[((size_t)b * NKV + g) * HD + d];
            g_att[(size_t)b * H + (g * NREP + rr) * HD + d] = tf32r(acc);
        }
        __syncthreads();
    }
}

// ---------------- launch ----------------
extern "C" void kernel_launch(void* const* d_in, const int* in_sizes, int n_in,
                              void* d_out, int out_size)
{
    const float* x  = (const float*)d_in[0];
    const float* kc = (const float*)d_in[1];
    const float* vc = (const float*)d_in[2];
    const float* nw = (const float*)d_in[3];
    const float* wq = (const float*)d_in[4];
    // d_in[5] (wk) provably does not affect the output: softmax over a
    // length-1 axis is identically 1, so new_out == v_new.
    const float* wv = (const float*)d_in[6];
    const float* wo = (const float*)d_in[7];
    float* out = (float*)d_out;

    int B = in_sizes[0] / H;                 // 128
    int L = in_sizes[1] / (B * NKV * HD);    // 1024
    int BH = B * H, BGD = B * NKV * HD;
    int units = B * NKV;                     // 1024
    int agrid = (units % 2 == 0) ? units / 2 : units;

    float *p_xn, *p_q, *p_vnew, *p_att;
    cudaGetSymbolAddress((void**)&p_xn,   g_xn);
    cudaGetSymbolAddress((void**)&p_q,    g_q);
    cudaGetSymbolAddress((void**)&p_vnew, g_vnew);
    cudaGetSymbolAddress((void**)&p_att,  g_att);

    cudaFuncSetAttribute(gemm_dual,   cudaFuncAttributeMaxDynamicSharedMemorySize, GEMM_SMEM);
    cudaFuncSetAttribute(gemm_single, cudaFuncAttributeMaxDynamicSharedMemorySize, GEMM_SMEM);

    int nbTotal = H / 128 + NKV * HD / 128;  // 32 + 8 = 40
    int zn = (BH + BGD + 255) / 256;
    prep_kernel<<<zn, 256>>>(BH, BGD, L);                                        // 0
    rmsnorm_kernel<<<B, 256>>>(x, nw);                                           // 1
    zero_kernel<<<(BH + 255) / 256, 256>>>(out, BH);                             // 2
    gemm_dual<<<DUAL_GRID, 256, GEMM_SMEM>>>(                                    // 3 <- profiled
        p_xn, wq, p_q, H, H / 128, wv, p_vnew, NKV * HD, H, nbTotal);
    attn_kernel<<<agrid, 256>>>(kc, vc, L, units);                               // 4
    gemm_single<<<dim3(H / 128, 8), 256, GEMM_SMEM>>>(p_att, wo, out, H, H);     // 5
}

// round 14
// speedup vs baseline: 1.0896x; 1.0896x over previous
#include <cuda_runtime.h>
#include <cuda_fp16.h>
#include <cstdint>
#include <math.h>

#define H        4096
#define HD       128
#define NKV      8
#define NREP     4
#define MAXB     128
#define MAXL     1024
#define SCP      (MAXL + 4)

// ---------------- scratch (no allocations allowed) ----------------
__device__ __half g_xnh[MAXB * H];
__device__ float  g_q[MAXB * H];
__device__ float  g_vnew[MAXB * NKV * HD];
__device__ __half g_atth[MAXB * H];
__device__ float  g_rope[HD];
__device__ int    g_ticket;

#define DUAL_GRID 296

// ---------------- prep: zero scratch, compute rope, reset ticket ----------
__global__ void prep_kernel(int BH, int BGD, int L) {
    int i = blockIdx.x * 256 + threadIdx.x;
    if (i < BH)            g_q[i] = 0.f;
    else if (i < BH + BGD) g_vnew[i - BH] = 0.f;
    if (i == 0) g_ticket = DUAL_GRID;
    if (blockIdx.x == 0 && threadIdx.x < HD / 2) {
        int t = threadIdx.x;
        double freq = exp(-((double)t / (double)HD) * 13.122363377404329); // ln(5e5)
        double ang  = (double)L * freq;
        double cv = cos(ang), sv = sin(ang);
        g_rope[t]          = (float)(cv - sv);
        g_rope[t + HD / 2] = (float)(cv + sv);
    }
}

__global__ void zero_kernel(float* __restrict__ p, int n) {
    int i = blockIdx.x * 256 + threadIdx.x;
    if (i < n) p[i] = 0.f;
}

// ---------------- rmsnorm (writes fp16 xn) ----------------
__global__ void rmsnorm_kernel(const float* __restrict__ x, const float* __restrict__ w) {
    int b = blockIdx.x;
    const float* xr = x + (size_t)b * H;
    float ss = 0.f;
    for (int i = threadIdx.x; i < H; i += 256) { float v = xr[i]; ss += v * v; }
    __shared__ float red[256];
    red[threadIdx.x] = ss;
    __syncthreads();
    for (int o = 128; o > 0; o >>= 1) {
        if (threadIdx.x < o) red[threadIdx.x] += red[threadIdx.x + o];
        __syncthreads();
    }
    float inv = rsqrtf(red[0] * (1.f / H) + 1e-5f);
    for (int i = threadIdx.x; i < H; i += 256)
        g_xnh[(size_t)b * H + i] = __float2half(xr[i] * inv * w[i]);
}

// ---- fp16 GEMM: CTA 128x128, warp 64x32, m16n8k16, f32 accumulate ----
__device__ __forceinline__ void cpa16(void* dst, const void* src) {
    uint32_t d = (uint32_t)__cvta_generic_to_shared(dst);
    asm volatile("cp.async.cg.shared.global [%0], [%1], 16;" :: "r"(d), "l"(src));
}
__device__ __forceinline__ void redv2(float* p, float v0, float v1) {
    asm volatile("red.global.add.v2.f32 [%0], {%1, %2};" :: "l"(p), "f"(v0), "f"(v1) : "memory");
}
__device__ __forceinline__ uint32_t packh2(float lo, float hi) {
    uint32_t r;
    asm("cvt.rn.f16x2.f32 %0, %1, %2;" : "=r"(r) : "f"(hi), "f"(lo));
    return r;
}

// stage layout (bytes within one stage)
#define ASTRH   40                           // A row stride in halves (pad)
#define A_BYTES (128 * ASTRH * 2)            // 10240
#define BPSTR   136                          // BP row stride in uint32 (pad)
#define BP_OFF  A_BYTES                      // 10240
#define BP_BYTES (16 * BPSTR * 4)            // 8704
#define RAW_OFF (BP_OFF + BP_BYTES)          // 18944
#define RAWSTR  136                          // raw fp32 row stride (pad)
#define RAW_BYTES (32 * RAWSTR * 4)          // 17408
#define STGB    (RAW_OFF + RAW_BYTES)        // 36352 per stage
#define GEMM_SMEM (2 * STGB)                 // 72704

// A: fp16 [M=128 rows][K halves]; B: fp32 [K][N]; C accumulated via red.v2.
__device__ __forceinline__ void gemm_core(
    const __half* __restrict__ A, const float* __restrict__ B, float* __restrict__ C,
    int K, int N, int n0, int kbeg, int kchunk, char* smc)
{
    int niter = kchunk / 32;
    int tid = threadIdx.x;
    int lane = tid & 31;
    int warp = tid >> 5;
    int mb = (warp >> 2) * 64;       // 2x4 warp grid over 128x128 tile
    int nb = (warp & 3) * 32;

    int lgrp = lane >> 3;
    int lrow = (lgrp & 1) * 8 + (lane & 7);
    int lcol = (lgrp >> 1) * 8;      // halves
    uint32_t smsh = (uint32_t)__cvta_generic_to_shared(smc);

    float c[4][4][4];
    #pragma unroll
    for (int i = 0; i < 4; i++)
        #pragma unroll
        for (int j = 0; j < 4; j++)
            #pragma unroll
            for (int k = 0; k < 4; k++) c[i][j][k] = 0.f;

    auto stage = [&](int buf, int k0) {
        char* base = smc + buf * STGB;
        // A: 128 rows x 32 halves (64B) -> 512 x 16B
        #pragma unroll
        for (int j = 0; j < 2; j++) {
            int id = tid + 256 * j;
            int row = id >> 2, seg = id & 3;
            cpa16(base + row * (ASTRH * 2) + seg * 16,
                  A + (size_t)row * K + k0 + seg * 8);
        }
        // B raw: 32 k-rows x 128 fp32 (512B) -> 1024 x 16B
        #pragma unroll
        for (int j = 0; j < 4; j++) {
            int id = tid + 256 * j;
            int row = id >> 5, nq = (id & 31) * 4;
            cpa16(base + RAW_OFF + (row * RAWSTR + nq) * 4,
                  B + (size_t)(k0 + row) * N + n0 + nq);
        }
        asm volatile("cp.async.commit_group;");
    };

    // convert raw fp32 B -> packed fp16 pairs BP[p][n] = (B[2p][n], B[2p+1][n])
    auto convert = [&](int buf) {
        char* base = smc + buf * STGB;
        const float* raw = (const float*)(base + RAW_OFF);
        uint32_t* bp = (uint32_t*)(base + BP_OFF);
        #pragma unroll
        for (int jj = 0; jj < 2; jj++) {
            int g = tid + 256 * jj;             // 512 groups of 4 outputs
            int p = g >> 5, n4 = (g & 31) * 4;
            float4 r0 = *(const float4*)(raw + (2 * p) * RAWSTR + n4);
            float4 r1 = *(const float4*)(raw + (2 * p + 1) * RAWSTR + n4);
            uint32_t o0 = packh2(r0.x, r1.x);
            uint32_t o1 = packh2(r0.y, r1.y);
            uint32_t o2 = packh2(r0.z, r1.z);
            uint32_t o3 = packh2(r0.w, r1.w);
            *(uint4*)(bp + p * BPSTR + n4) = make_uint4(o0, o1, o2, o3);
        }
    };

    stage(0, kbeg);
    for (int i = 0; i < niter; i++) {
        if (i + 1 < niter) {
            stage((i + 1) & 1, kbeg + (i + 1) * 32);
            asm volatile("cp.async.wait_group 1;");
        } else {
            asm volatile("cp.async.wait_group 0;");
        }
        __syncthreads();
        convert(i & 1);
        __syncthreads();

        uint32_t Ash = smsh + (uint32_t)((i & 1) * STGB);
        const uint32_t* bp = (const uint32_t*)(smc + (i & 1) * STGB + BP_OFF);
        #pragma unroll
        for (int ks = 0; ks < 2; ks++) {        // two k16 steps
            uint32_t a[4][4], bf[4][2];
            #pragma unroll
            for (int im = 0; im < 4; im++) {
                uint32_t adr = Ash + (uint32_t)((mb + im * 16 + lrow) * ASTRH
                                                + ks * 16 + lcol) * 2;
                asm volatile(
                    "ldmatrix.sync.aligned.m8n8.x4.shared.b16 {%0,%1,%2,%3}, [%4];"
                    : "=r"(a[im][0]), "=r"(a[im][1]), "=r"(a[im][2]), "=r"(a[im][3])
                    : "r"(adr));
            }
            #pragma unroll
            for (int jn = 0; jn < 4; jn++) {
                int n = nb + jn * 8 + (lane >> 2);
                bf[jn][0] = bp[(ks * 8 + (lane & 3)) * BPSTR + n];
                bf[jn][1] = bp[(ks * 8 + 4 + (lane & 3)) * BPSTR + n];
            }
            #pragma unroll
            for (int im = 0; im < 4; im++)
                #pragma unroll
                for (int jn = 0; jn < 4; jn++)
                    asm volatile(
                        "mma.sync.aligned.m16n8k16.row.col.f32.f16.f16.f32 "
                        "{%0,%1,%2,%3},{%4,%5,%6,%7},{%8,%9},{%0,%1,%2,%3};"
                        : "+f"(c[im][jn][0]), "+f"(c[im][jn][1]),
                          "+f"(c[im][jn][2]), "+f"(c[im][jn][3])
                        : "r"(a[im][0]), "r"(a[im][1]), "r"(a[im][2]), "r"(a[im][3]),
                          "r"(bf[jn][0]), "r"(bf[jn][1]));
        }
        __syncthreads();   // A[buf] fully consumed before it is restaged
    }

    #pragma unroll
    for (int im = 0; im < 4; im++) {
        int r = mb + im * 16 + (lane >> 2);
        #pragma unroll
        for (int jn = 0; jn < 4; jn++) {
            int col = n0 + nb + jn * 8 + (lane & 3) * 2;
            redv2(&C[(size_t)r * N + col],       c[im][jn][0], c[im][jn][1]);
            redv2(&C[(size_t)(r + 8) * N + col], c[im][jn][2], c[im][jn][3]);
        }
    }
    __syncthreads();   // smem safe before next persistent item stages
}

// persistent dual GEMM (wq + wv) with ticket work-stealing
#define DUAL_KS 16
__global__ void __launch_bounds__(256, 2) gemm_dual(
    const __half* __restrict__ A,
    const float* __restrict__ B1, float* __restrict__ C1, int N1, int nb1,
    const float* __restrict__ B2, float* __restrict__ C2, int N2, int K,
    int nbTotal)
{
    extern __shared__ char smc[];
    __shared__ int s_item;
    int kchunk = K / DUAL_KS;                 // 256
    int nItems = nbTotal * DUAL_KS;           // 640
    int item = blockIdx.x;
    while (item < nItems) {
        int nb = item % nbTotal;
        int ks = item / nbTotal;
        if (nb < nb1) gemm_core(A, B1, C1, K, N1, nb * 128, ks * kchunk, kchunk, smc);
        else          gemm_core(A, B2, C2, K, N2, (nb - nb1) * 128, ks * kchunk, kchunk, smc);
        if (threadIdx.x == 0) s_item = atomicAdd(&g_ticket, 1);
        __syncthreads();
        item = s_item;
    }
}

__global__ void __launch_bounds__(256, 2) gemm_single(
    const __half* __restrict__ A, const float* __restrict__ B, float* __restrict__ C,
    int N, int K)
{
    extern __shared__ char smc[];
    int kchunk = K / gridDim.y;
    gemm_core(A, B, C, K, N, blockIdx.x * 128, blockIdx.y * kchunk, kchunk, smc);
}

// ---------------- attention: persistent CTAs, warp-local softmax ----------
__global__ void __launch_bounds__(256, 4) attn_kernel(
    const float* __restrict__ Kc, const float* __restrict__ Vc, int L, int units)
{
    __shared__ float sc[NREP][SCP];
    __shared__ float pout[8][NREP][HD];
    __shared__ float wm[8][NREP], ws[8][NREP];
    __shared__ float fac[8][NREP], gsum[NREP];

    int t = threadIdx.x, lane = t & 31, w = t >> 5;
    bool hi16 = (lane & 16) != 0, hi8 = (lane & 8) != 0;
    float4 rp = *(const float4*)(g_rope + lane * 4);

    for (int bg = blockIdx.x; bg < units; bg += gridDim.x) {
        int b = bg >> 3, g = bg & 7;

        float4 q[NREP];
        #pragma unroll
        for (int r = 0; r < NREP; r++) {
            float4 qv = *(const float4*)(g_q + (size_t)b * H + (g * NREP + r) * HD + lane * 4);
            q[r].x = qv.x * rp.x * 0.08838834764831845f;
            q[r].y = qv.y * rp.y * 0.08838834764831845f;
            q[r].z = qv.z * rp.z * 0.08838834764831845f;
            q[r].w = qv.w * rp.w * 0.08838834764831845f;
        }

        const float* Kb = Kc + (size_t)bg * L * HD;
        int lbeg = w * (L >> 3);
        int lend = lbeg + (L >> 3);
        const float* kp = Kb + (size_t)lbeg * HD + lane * 4;
        float mloc = -1e30f;
        for (int l = lbeg; l < lend; l += 4, kp += 4 * HD) {
            float4 k0 = *(const float4*)kp;
            float4 k1 = *(const float4*)(kp + HD);
            float4 k2 = *(const float4*)(kp + 2 * HD);
            float4 k3 = *(const float4*)(kp + 3 * HD);

            #pragma unroll
            for (int pair = 0; pair < 2; pair++) {
                float4 ka = pair ? k2 : k0;
                float4 kb = pair ? k3 : k1;
                float p0[4], p1[4];
                #pragma unroll
                for (int r = 0; r < 4; r++) {
                    p0[r] = ka.x * q[r].x + ka.y * q[r].y + ka.z * q[r].z + ka.w * q[r].w;
                    p1[r] = kb.x * q[r].x + kb.y * q[r].y + kb.z * q[r].z + kb.w * q[r].w;
                }
                float a0 = hi16 ? p0[2] : p0[0];
                float a1 = hi16 ? p0[3] : p0[1];
                a0 += __shfl_xor_sync(0xffffffffu, hi16 ? p0[0] : p0[2], 16);
                a1 += __shfl_xor_sync(0xffffffffu, hi16 ? p0[1] : p0[3], 16);
                float c0 = hi8 ? a1 : a0;
                c0 += __shfl_xor_sync(0xffffffffu, hi8 ? a0 : a1, 8);
                c0 += __shfl_xor_sync(0xffffffffu, c0, 4);
                c0 += __shfl_xor_sync(0xffffffffu, c0, 2);
                c0 += __shfl_xor_sync(0xffffffffu, c0, 1);

                float b0 = hi16 ? p1[2] : p1[0];
                float b1 = hi16 ? p1[3] : p1[1];
                b0 += __shfl_xor_sync(0xffffffffu, hi16 ? p1[0] : p1[2], 16);
                b1 += __shfl_xor_sync(0xffffffffu, hi16 ? p1[1] : p1[3], 16);
                float c1 = hi8 ? b1 : b0;
                c1 += __shfl_xor_sync(0xffffffffu, hi8 ? b0 : b1, 8);
                c1 += __shfl_xor_sync(0xffffffffu, c1, 4);
                c1 += __shfl_xor_sync(0xffffffffu, c1, 2);
                c1 += __shfl_xor_sync(0xffffffffu, c1, 1);

                mloc = fmaxf(mloc, fmaxf(c0, c1));
                if ((lane & 7) == 0) {
                    int r = lane >> 3;
                    sc[r][l + pair * 2]     = c0;
                    sc[r][l + pair * 2 + 1] = c1;
                }
            }
        }
        __syncwarp();

        int r0i = lane >> 3, cix = lane & 7;
        float s_w = 0.f;
        int pcnt = L >> 6;
        for (int j = 0; j < pcnt; j++) {
            int l = lbeg + cix + j * 8;
            float p = __expf(sc[r0i][l] - mloc);
            sc[r0i][l] = p;
            s_w += p;
        }
        s_w += __shfl_xor_sync(0xffffffffu, s_w, 4);
        s_w += __shfl_xor_sync(0xffffffffu, s_w, 2);
        s_w += __shfl_xor_sync(0xffffffffu, s_w, 1);
        __syncwarp();

        const float* Vb = Vc + (size_t)bg * L * HD;
        const float* vp = Vb + (size_t)lbeg * HD + lane * 4;
        float4 o0 = {0,0,0,0}, o1 = o0, o2 = o0, o3 = o0;
        for (int l = lbeg; l < lend; l += 4, vp += 4 * HD) {
            float4 v0 = *(const float4*)vp;
            float4 v1 = *(const float4*)(vp + HD);
            float4 v2 = *(const float4*)(vp + 2 * HD);
            float4 v3 = *(const float4*)(vp + 3 * HD);
            float4 pa = *(const float4*)&sc[0][l];
            float4 pb = *(const float4*)&sc[1][l];
            float4 pc = *(const float4*)&sc[2][l];
            float4 pd = *(const float4*)&sc[3][l];
            o0.x += pa.x*v0.x + pa.y*v1.x + pa.z*v2.x + pa.w*v3.x;
            o0.y += pa.x*v0.y + pa.y*v1.y + pa.z*v2.y + pa.w*v3.y;
            o0.z += pa.x*v0.z + pa.y*v1.z + pa.z*v2.z + pa.w*v3.z;
            o0.w += pa.x*v0.w + pa.y*v1.w + pa.z*v2.w + pa.w*v3.w;
            o1.x += pb.x*v0.x + pb.y*v1.x + pb.z*v2.x + pb.w*v3.x;
            o1.y += pb.x*v0.y + pb.y*v1.y + pb.z*v2.y + pb.w*v3.y;
            o1.z += pb.x*v0.z + pb.y*v1.z + pb.z*v2.z + pb.w*v3.z;
            o1.w += pb.x*v0.w + pb.y*v1.w + pb.z*v2.w + pb.w*v3.w;
            o2.x += pc.x*v0.x + pc.y*v1.x + pc.z*v2.x + pc.w*v3.x;
            o2.y += pc.x*v0.y + pc.y*v1.y + pc.z*v2.y + pc.w*v3.y;
            o2.z += pc.x*v0.z + pc.y*v1.z + pc.z*v2.z + pc.w*v3.z;
            o2.w += pc.x*v0.w + pc.y*v1.w + pc.z*v2.w + pc.w*v3.w;
            o3.x += pd.x*v0.x + pd.y*v1.x + pd.z*v2.x + pd.w*v3.x;
            o3.y += pd.x*v0.y + pd.y*v1.y + pd.z*v2.y + pd.w*v3.y;
            o3.z += pd.x*v0.z + pd.y*v1.z + pd.z*v2.z + pd.w*v3.z;
            o3.w += pd.x*v0.w + pd.y*v1.w + pd.z*v2.w + pd.w*v3.w;
        }
        ((float4*)&pout[w][0][0])[lane] = o0;
        ((float4*)&pout[w][1][0])[lane] = o1;
        ((float4*)&pout[w][2][0])[lane] = o2;
        ((float4*)&pout[w][3][0])[lane] = o3;
        if ((lane & 7) == 0) {
            wm[w][r0i] = mloc;
            ws[w][r0i] = s_w;
        }
        __syncthreads();

        if (t < NREP) {
            float mg = -1e30f;
            #pragma unroll
            for (int ww = 0; ww < 8; ww++) mg = fmaxf(mg, wm[ww][t]);
            float sg = 0.f;
            #pragma unroll
            for (int ww = 0; ww < 8; ww++) {
                float f = __expf(wm[ww][t] - mg);
                fac[ww][t] = f;
                sg += ws[ww][t] * f;
            }
            gsum[t] = sg;
        }
        __syncthreads();

        // reduce, normalize, add v_new; store fp16 for the wo GEMM
        for (int i = t; i < NREP * HD; i += 256) {
            int rr = i >> 7, d = i & (HD - 1);
            float acc = 0.f;
            #pragma unroll
            for (int gg = 0; gg < 8; gg++) acc += pout[gg][rr][d] * fac[gg][rr];
            acc = acc / gsum[rr] + g_vnew[((size_t)b * NKV + g) * HD + d];
            g_atth[(size_t)b * H + (g * NREP + rr) * HD + d] = __float2half(acc);
        }
        __syncthreads();
    }
}

// ---------------- launch ----------------
extern "C" void kernel_launch(void* const* d_in, const int* in_sizes, int n_in,
                              void* d_out, int out_size)
{
    const float* x  = (const float*)d_in[0];
    const float* kc = (const float*)d_in[1];
    const float* vc = (const float*)d_in[2];
    const float* nw = (const float*)d_in[3];
    const float* wq = (const float*)d_in[4];
    // d_in[5] (wk) provably does not affect the output: softmax over a
    // length-1 axis is identically 1, so new_out == v_new.
    const float* wv = (const float*)d_in[6];
    const float* wo = (const float*)d_in[7];
    float* out = (float*)d_out;

    int B = in_sizes[0] / H;                 // 128
    int L = in_sizes[1] / (B * NKV * HD);    // 1024
    int BH = B * H, BGD = B * NKV * HD;
    int units = B * NKV;                     // 1024
    int agrid = (units % 2 == 0) ? units / 2 : units;

    __half *p_xnh, *p_atth;
    float *p_q, *p_vnew;
    cudaGetSymbolAddress((void**)&p_xnh,  g_xnh);
    cudaGetSymbolAddress((void**)&p_q,    g_q);
    cudaGetSymbolAddress((void**)&p_vnew, g_vnew);
    cudaGetSymbolAddress((void**)&p_atth, g_atth);

    cudaFuncSetAttribute(gemm_dual,   cudaFuncAttributeMaxDynamicSharedMemorySize, GEMM_SMEM);
    cudaFuncSetAttribute(gemm_single, cudaFuncAttributeMaxDynamicSharedMemorySize, GEMM_SMEM);

    int nbTotal = H / 128 + NKV * HD / 128;  // 32 + 8 = 40
    int zn = (BH + BGD + 255) / 256;
    prep_kernel<<<zn, 256>>>(BH, BGD, L);                                        // 0
    rmsnorm_kernel<<<B, 256>>>(x, nw);                                           // 1
    zero_kernel<<<(BH + 255) / 256, 256>>>(out, BH);                             // 2
    gemm_dual<<<DUAL_GRID, 256, GEMM_SMEM>>>(                                    // 3 <- profiled
        p_xnh, wq, p_q, H, H / 128, wv, p_vnew, NKV * HD, H, nbTotal);
    attn_kernel<<<agrid, 256>>>(kc, vc, L, units);                               // 4
    gemm_single<<<dim3(H / 128, 8), 256, GEMM_SMEM>>>(p_atth, wo, out, H, H);    // 5
}

// round 15
// speedup vs baseline: 1.1102x; 1.0189x over previous
#include <cuda_runtime.h>
#include <cuda_fp16.h>
#include <cstdint>
#include <math.h>

#define H        4096
#define HD       128
#define NKV      8
#define NREP     4
#define MAXB     128
#define MAXL     1024
#define SCP      (MAXL + 4)

// ---------------- scratch (no allocations allowed) ----------------
__device__ __half g_xnh[MAXB * H];
__device__ float  g_q[MAXB * H];
__device__ float  g_vnew[MAXB * NKV * HD];
__device__ __half g_atth[MAXB * H];
__device__ float  g_rope[HD];
__device__ int    g_ticket;

#define DUAL_GRID 296

// ---------------- prep: zero scratch, compute rope, reset ticket ----------
__global__ void prep_kernel(int BH, int BGD, int L) {
    int i = blockIdx.x * 256 + threadIdx.x;
    if (i < BH)            g_q[i] = 0.f;
    else if (i < BH + BGD) g_vnew[i - BH] = 0.f;
    if (i == 0) g_ticket = DUAL_GRID;
    if (blockIdx.x == 0 && threadIdx.x < HD / 2) {
        int t = threadIdx.x;
        double freq = exp(-((double)t / (double)HD) * 13.122363377404329); // ln(5e5)
        double ang  = (double)L * freq;
        double cv = cos(ang), sv = sin(ang);
        g_rope[t]          = (float)(cv - sv);
        g_rope[t + HD / 2] = (float)(cv + sv);
    }
}

__global__ void zero_kernel(float* __restrict__ p, int n) {
    int i = blockIdx.x * 256 + threadIdx.x;
    if (i < n) p[i] = 0.f;
}

// ---------------- rmsnorm (writes fp16 xn) ----------------
__global__ void rmsnorm_kernel(const float* __restrict__ x, const float* __restrict__ w) {
    int b = blockIdx.x;
    const float* xr = x + (size_t)b * H;
    float ss = 0.f;
    for (int i = threadIdx.x; i < H; i += 256) { float v = xr[i]; ss += v * v; }
    __shared__ float red[256];
    red[threadIdx.x] = ss;
    __syncthreads();
    for (int o = 128; o > 0; o >>= 1) {
        if (threadIdx.x < o) red[threadIdx.x] += red[threadIdx.x + o];
        __syncthreads();
    }
    float inv = rsqrtf(red[0] * (1.f / H) + 1e-5f);
    for (int i = threadIdx.x; i < H; i += 256)
        g_xnh[(size_t)b * H + i] = __float2half(xr[i] * inv * w[i]);
}

// ---- fp16 GEMM: CTA 128x128, warp 64x32, m16n8k16, inline B cvt ----
__device__ __forceinline__ void cpa16(void* dst, const void* src) {
    uint32_t d = (uint32_t)__cvta_generic_to_shared(dst);
    asm volatile("cp.async.cg.shared.global [%0], [%1], 16;" :: "r"(d), "l"(src));
}
__device__ __forceinline__ void redv2(float* p, float v0, float v1) {
    asm volatile("red.global.add.v2.f32 [%0], {%1, %2};" :: "l"(p), "f"(v0), "f"(v1) : "memory");
}
__device__ __forceinline__ uint32_t packh2(float lo, float hi) {
    uint32_t r;
    asm("cvt.rn.f16x2.f32 %0, %1, %2;" : "=r"(r) : "f"(hi), "f"(lo));
    return r;
}

// stage layout (bytes within one stage)
#define ASTRH   40                           // A row stride in halves (80B, conflict-free LDSM)
#define A_BYTES (128 * ASTRH * 2)            // 10240
#define BSTR    140                          // B raw fp32 row stride in floats (disjoint banks)
#define B_OFF   A_BYTES
#define B_BYTES (32 * BSTR * 4)              // 17920
#define STGB    (A_BYTES + B_BYTES)          // 28160 per stage
#define GEMM_SMEM (2 * STGB)                 // 56320

// A: fp16 [M=128 rows][K halves]; B: fp32 [K][N]; C accumulated via red.v2.
__device__ __forceinline__ void gemm_core(
    const __half* __restrict__ A, const float* __restrict__ B, float* __restrict__ C,
    int K, int N, int n0, int kbeg, int kchunk, char* smc)
{
    int niter = kchunk / 32;
    int tid = threadIdx.x;
    int lane = tid & 31;
    int warp = tid >> 5;
    int mb = (warp >> 2) * 64;       // 2x4 warp grid over 128x128 tile
    int nb = (warp & 3) * 32;

    int lgrp = lane >> 3;
    int lrow = (lgrp & 1) * 8 + (lane & 7);
    int lcol = (lgrp >> 1) * 8;      // halves
    uint32_t smsh = (uint32_t)__cvta_generic_to_shared(smc);

    float c[4][4][4];
    #pragma unroll
    for (int i = 0; i < 4; i++)
        #pragma unroll
        for (int j = 0; j < 4; j++)
            #pragma unroll
            for (int k = 0; k < 4; k++) c[i][j][k] = 0.f;

    auto stage = [&](int buf, int k0) {
        char* base = smc + buf * STGB;
        // A: 128 rows x 32 halves (64B) -> 512 x 16B
        #pragma unroll
        for (int j = 0; j < 2; j++) {
            int id = tid + 256 * j;
            int row = id >> 2, seg = id & 3;
            cpa16(base + row * (ASTRH * 2) + seg * 16,
                  A + (size_t)row * K + k0 + seg * 8);
        }
        // B raw: 32 k-rows x 128 fp32 (512B) -> 1024 x 16B
        #pragma unroll
        for (int j = 0; j < 4; j++) {
            int id = tid + 256 * j;
            int row = id >> 5, nq = (id & 31) * 4;
            cpa16(base + B_OFF + (row * BSTR + nq) * 4,
                  B + (size_t)(k0 + row) * N + n0 + nq);
        }
        asm volatile("cp.async.commit_group;");
    };

    stage(0, kbeg);
    for (int i = 0; i < niter; i++) {
        if (i + 1 < niter) {
            stage((i + 1) & 1, kbeg + (i + 1) * 32);
            asm volatile("cp.async.wait_group 1;");
        } else {
            asm volatile("cp.async.wait_group 0;");
        }
        __syncthreads();

        uint32_t Ash = smsh + (uint32_t)((i & 1) * STGB);
        const float* raw = (const float*)(smc + (i & 1) * STGB + B_OFF);
        #pragma unroll
        for (int ks = 0; ks < 2; ks++) {        // two k16 steps
            uint32_t a[4][4], bf[4][2];
            #pragma unroll
            for (int im = 0; im < 4; im++) {
                uint32_t adr = Ash + (uint32_t)((mb + im * 16 + lrow) * ASTRH
                                                + ks * 16 + lcol) * 2;
                asm volatile(
                    "ldmatrix.sync.aligned.m8n8.x4.shared.b16 {%0,%1,%2,%3}, [%4];"
                    : "=r"(a[im][0]), "=r"(a[im][1]), "=r"(a[im][2]), "=r"(a[im][3])
                    : "r"(adr));
            }
            #pragma unroll
            for (int jn = 0; jn < 4; jn++) {
                int n = nb + jn * 8 + (lane >> 2);
                int kq = ks * 16 + (lane & 3) * 2;
                bf[jn][0] = packh2(raw[kq * BSTR + n],       raw[(kq + 1) * BSTR + n]);
                bf[jn][1] = packh2(raw[(kq + 8) * BSTR + n], raw[(kq + 9) * BSTR + n]);
            }
            #pragma unroll
            for (int im = 0; im < 4; im++)
                #pragma unroll
                for (int jn = 0; jn < 4; jn++)
                    asm volatile(
                        "mma.sync.aligned.m16n8k16.row.col.f32.f16.f16.f32 "
                        "{%0,%1,%2,%3},{%4,%5,%6,%7},{%8,%9},{%0,%1,%2,%3};"
                        : "+f"(c[im][jn][0]), "+f"(c[im][jn][1]),
                          "+f"(c[im][jn][2]), "+f"(c[im][jn][3])
                        : "r"(a[im][0]), "r"(a[im][1]), "r"(a[im][2]), "r"(a[im][3]),
                          "r"(bf[jn][0]), "r"(bf[jn][1]));
        }
        __syncthreads();   // buffer fully consumed before it is restaged
    }

    #pragma unroll
    for (int im = 0; im < 4; im++) {
        int r = mb + im * 16 + (lane >> 2);
        #pragma unroll
        for (int jn = 0; jn < 4; jn++) {
            int col = n0 + nb + jn * 8 + (lane & 3) * 2;
            redv2(&C[(size_t)r * N + col],       c[im][jn][0], c[im][jn][1]);
            redv2(&C[(size_t)(r + 8) * N + col], c[im][jn][2], c[im][jn][3]);
        }
    }
    __syncthreads();   // smem safe before next persistent item stages
}

// persistent dual GEMM (wq + wv) with ticket work-stealing
#define DUAL_KS 16
__global__ void __launch_bounds__(256, 2) gemm_dual(
    const __half* __restrict__ A,
    const float* __restrict__ B1, float* __restrict__ C1, int N1, int nb1,
    const float* __restrict__ B2, float* __restrict__ C2, int N2, int K,
    int nbTotal)
{
    extern __shared__ char smc[];
    __shared__ int s_item;
    int kchunk = K / DUAL_KS;                 // 256
    int nItems = nbTotal * DUAL_KS;           // 640
    int item = blockIdx.x;
    while (item < nItems) {
        int nb = item % nbTotal;
        int ks = item / nbTotal;
        if (nb < nb1) gemm_core(A, B1, C1, K, N1, nb * 128, ks * kchunk, kchunk, smc);
        else          gemm_core(A, B2, C2, K, N2, (nb - nb1) * 128, ks * kchunk, kchunk, smc);
        if (threadIdx.x == 0) s_item = atomicAdd(&g_ticket, 1);
        __syncthreads();
        item = s_item;
    }
}

__global__ void __launch_bounds__(256, 2) gemm_single(
    const __half* __restrict__ A, const float* __restrict__ B, float* __restrict__ C,
    int N, int K)
{
    extern __shared__ char smc[];
    int kchunk = K / gridDim.y;
    gemm_core(A, B, C, K, N, blockIdx.x * 128, blockIdx.y * kchunk, kchunk, smc);
}

// ---------------- attention: persistent CTAs, warp-local softmax ----------
__global__ void __launch_bounds__(256, 4) attn_kernel(
    const float* __restrict__ Kc, const float* __restrict__ Vc, int L, int units)
{
    __shared__ float sc[NREP][SCP];
    __shared__ float pout[8][NREP][HD];
    __shared__ float wm[8][NREP], ws[8][NREP];
    __shared__ float fac[8][NREP], gsum[NREP];

    int t = threadIdx.x, lane = t & 31, w = t >> 5;
    bool hi16 = (lane & 16) != 0, hi8 = (lane & 8) != 0;
    float4 rp = *(const float4*)(g_rope + lane * 4);

    for (int bg = blockIdx.x; bg < units; bg += gridDim.x) {
        int b = bg >> 3, g = bg & 7;

        float4 q[NREP];
        #pragma unroll
        for (int r = 0; r < NREP; r++) {
            float4 qv = *(const float4*)(g_q + (size_t)b * H + (g * NREP + r) * HD + lane * 4);
            q[r].x = qv.x * rp.x * 0.08838834764831845f;
            q[r].y = qv.y * rp.y * 0.08838834764831845f;
            q[r].z = qv.z * rp.z * 0.08838834764831845f;
            q[r].w = qv.w * rp.w * 0.08838834764831845f;
        }

        const float* Kb = Kc + (size_t)bg * L * HD;
        int lbeg = w * (L >> 3);
        int lend = lbeg + (L >> 3);
        const float* kp = Kb + (size_t)lbeg * HD + lane * 4;
        float mloc = -1e30f;
        for (int l = lbeg; l < lend; l += 4, kp += 4 * HD) {
            float4 k0 = *(const float4*)kp;
            float4 k1 = *(const float4*)(kp + HD);
            float4 k2 = *(const float4*)(kp + 2 * HD);
            float4 k3 = *(const float4*)(kp + 3 * HD);

            #pragma unroll
            for (int pair = 0; pair < 2; pair++) {
                float4 ka = pair ? k2 : k0;
                float4 kb = pair ? k3 : k1;
                float p0[4], p1[4];
                #pragma unroll
                for (int r = 0; r < 4; r++) {
                    p0[r] = ka.x * q[r].x + ka.y * q[r].y + ka.z * q[r].z + ka.w * q[r].w;
                    p1[r] = kb.x * q[r].x + kb.y * q[r].y + kb.z * q[r].z + kb.w * q[r].w;
                }
                float a0 = hi16 ? p0[2] : p0[0];
                float a1 = hi16 ? p0[3] : p0[1];
                a0 += __shfl_xor_sync(0xffffffffu, hi16 ? p0[0] : p0[2], 16);
                a1 += __shfl_xor_sync(0xffffffffu, hi16 ? p0[1] : p0[3], 16);
                float c0 = hi8 ? a1 : a0;
                c0 += __shfl_xor_sync(0xffffffffu, hi8 ? a0 : a1, 8);
                c0 += __shfl_xor_sync(0xffffffffu, c0, 4);
                c0 += __shfl_xor_sync(0xffffffffu, c0, 2);
                c0 += __shfl_xor_sync(0xffffffffu, c0, 1);

                float b0 = hi16 ? p1[2] : p1[0];
                float b1 = hi16 ? p1[3] : p1[1];
                b0 += __shfl_xor_sync(0xffffffffu, hi16 ? p1[0] : p1[2], 16);
                b1 += __shfl_xor_sync(0xffffffffu, hi16 ? p1[1] : p1[3], 16);
                float c1 = hi8 ? b1 : b0;
                c1 += __shfl_xor_sync(0xffffffffu, hi8 ? b0 : b1, 8);
                c1 += __shfl_xor_sync(0xffffffffu, c1, 4);
                c1 += __shfl_xor_sync(0xffffffffu, c1, 2);
                c1 += __shfl_xor_sync(0xffffffffu, c1, 1);

                mloc = fmaxf(mloc, fmaxf(c0, c1));
                if ((lane & 7) == 0) {
                    int r = lane >> 3;
                    sc[r][l + pair * 2]     = c0;
                    sc[r][l + pair * 2 + 1] = c1;
                }
            }
        }
        __syncwarp();

        int r0i = lane >> 3, cix = lane & 7;
        float s_w = 0.f;
        int pcnt = L >> 6;
        for (int j = 0; j < pcnt; j++) {
            int l = lbeg + cix + j * 8;
            float p = __expf(sc[r0i][l] - mloc);
            sc[r0i][l] = p;
            s_w += p;
        }
        s_w += __shfl_xor_sync(0xffffffffu, s_w, 4);
        s_w += __shfl_xor_sync(0xffffffffu, s_w, 2);
        s_w += __shfl_xor_sync(0xffffffffu, s_w, 1);
        __syncwarp();

        const float* Vb = Vc + (size_t)bg * L * HD;
        const float* vp = Vb + (size_t)lbeg * HD + lane * 4;
        float4 o0 = {0,0,0,0}, o1 = o0, o2 = o0, o3 = o0;
        for (int l = lbeg; l < lend; l += 4, vp += 4 * HD) {
            float4 v0 = *(const float4*)vp;
            float4 v1 = *(const float4*)(vp + HD);
            float4 v2 = *(const float4*)(vp + 2 * HD);
            float4 v3 = *(const float4*)(vp + 3 * HD);
            float4 pa = *(const float4*)&sc[0][l];
            float4 pb = *(const float4*)&sc[1][l];
            float4 pc = *(const float4*)&sc[2][l];
            float4 pd = *(const float4*)&sc[3][l];
            o0.x += pa.x*v0.x + pa.y*v1.x + pa.z*v2.x + pa.w*v3.x;
            o0.y += pa.x*v0.y + pa.y*v1.y + pa.z*v2.y + pa.w*v3.y;
            o0.z += pa.x*v0.z + pa.y*v1.z + pa.z*v2.z + pa.w*v3.z;
            o0.w += pa.x*v0.w + pa.y*v1.w + pa.z*v2.w + pa.w*v3.w;
            o1.x += pb.x*v0.x + pb.y*v1.x + pb.z*v2.x + pb.w*v3.x;
            o1.y += pb.x*v0.y + pb.y*v1.y + pb.z*v2.y + pb.w*v3.y;
            o1.z += pb.x*v0.z + pb.y*v1.z + pb.z*v2.z + pb.w*v3.z;
            o1.w += pb.x*v0.w + pb.y*v1.w + pb.z*v2.w + pb.w*v3.w;
            o2.x += pc.x*v0.x + pc.y*v1.x + pc.z*v2.x + pc.w*v3.x;
            o2.y += pc.x*v0.y + pc.y*v1.y + pc.z*v2.y + pc.w*v3.y;
            o2.z += pc.x*v0.z + pc.y*v1.z + pc.z*v2.z + pc.w*v3.z;
            o2.w += pc.x*v0.w + pc.y*v1.w + pc.z*v2.w + pc.w*v3.w;
            o3.x += pd.x*v0.x + pd.y*v1.x + pd.z*v2.x + pd.w*v3.x;
            o3.y += pd.x*v0.y + pd.y*v1.y + pd.z*v2.y + pd.w*v3.y;
            o3.z += pd.x*v0.z + pd.y*v1.z + pd.z*v2.z + pd.w*v3.z;
            o3.w += pd.x*v0.w + pd.y*v1.w + pd.z*v2.w + pd.w*v3.w;
        }
        ((float4*)&pout[w][0][0])[lane] = o0;
        ((float4*)&pout[w][1][0])[lane] = o1;
        ((float4*)&pout[w][2][0])[lane] = o2;
        ((float4*)&pout[w][3][0])[lane] = o3;
        if ((lane & 7) == 0) {
            wm[w][r0i] = mloc;
            ws[w][r0i] = s_w;
        }
        __syncthreads();

        if (t < NREP) {
            float mg = -1e30f;
            #pragma unroll
            for (int ww = 0; ww < 8; ww++) mg = fmaxf(mg, wm[ww][t]);
            float sg = 0.f;
            #pragma unroll
            for (int ww = 0; ww < 8; ww++) {
                float f = __expf(wm[ww][t] - mg);
                fac[ww][t] = f;
                sg += ws[ww][t] * f;
            }
            gsum[t] = sg;
        }
        __syncthreads();

        // reduce, normalize, add v_new; store fp16 for the wo GEMM
        for (int i = t; i < NREP * HD; i += 256) {
            int rr = i >> 7, d = i & (HD - 1);
            float acc = 0.f;
            #pragma unroll
            for (int gg = 0; gg < 8; gg++) acc += pout[gg][rr][d] * fac[gg][rr];
            acc = acc / gsum[rr] + g_vnew[((size_t)b * NKV + g) * HD + d];
            g_atth[(size_t)b * H + (g * NREP + rr) * HD + d] = __float2half(acc);
        }
        __syncthreads();
    }
}

// ---------------- launch ----------------
extern "C" void kernel_launch(void* const* d_in, const int* in_sizes, int n_in,
                              void* d_out, int out_size)
{
    const float* x  = (const float*)d_in[0];
    const float* kc = (const float*)d_in[1];
    const float* vc = (const float*)d_in[2];
    const float* nw = (const float*)d_in[3];
    const float* wq = (const float*)d_in[4];
    // d_in[5] (wk) provably does not affect the output: softmax over a
    // length-1 axis is identically 1, so new_out == v_new.
    const float* wv = (const float*)d_in[6];
    const float* wo = (const float*)d_in[7];
    float* out = (float*)d_out;

    int B = in_sizes[0] / H;                 // 128
    int L = in_sizes[1] / (B * NKV * HD);    // 1024
    int BH = B * H, BGD = B * NKV * HD;
    int units = B * NKV;                     // 1024
    int agrid = (units % 2 == 0) ? units / 2 : units;

    __half *p_xnh, *p_atth;
    float *p_q, *p_vnew;
    cudaGetSymbolAddress((void**)&p_xnh,  g_xnh);
    cudaGetSymbolAddress((void**)&p_q,    g_q);
    cudaGetSymbolAddress((void**)&p_vnew, g_vnew);
    cudaGetSymbolAddress((void**)&p_atth, g_atth);

    cudaFuncSetAttribute(gemm_dual,   cudaFuncAttributeMaxDynamicSharedMemorySize, GEMM_SMEM);
    cudaFuncSetAttribute(gemm_single, cudaFuncAttributeMaxDynamicSharedMemorySize, GEMM_SMEM);

    int nbTotal = H / 128 + NKV * HD / 128;  // 32 + 8 = 40
    int zn = (BH + BGD + 255) / 256;
    prep_kernel<<<zn, 256>>>(BH, BGD, L);                                        // 0
    rmsnorm_kernel<<<B, 256>>>(x, nw);                                           // 1
    zero_kernel<<<(BH + 255) / 256, 256>>>(out, BH);                             // 2
    gemm_dual<<<DUAL_GRID, 256, GEMM_SMEM>>>(                                    // 3 <- profiled
        p_xnh, wq, p_q, H, H / 128, wv, p_vnew, NKV * HD, H, nbTotal);
    attn_kernel<<<agrid, 256>>>(kc, vc, L, units);                               // 4
    gemm_single<<<dim3(H / 128, 8), 256, GEMM_SMEM>>>(p_atth, wo, out, H, H);    // 5
}

// round 16
// speedup vs baseline: 1.1207x; 1.0094x over previous
#include <cuda_runtime.h>
#include <cuda_fp16.h>
#include <cstdint>
#include <math.h>

#define H        4096
#define HD       128
#define NKV      8
#define NREP     4
#define MAXB     128
#define MAXL     1024
#define SCP      (MAXL + 4)

// ---------------- scratch (no allocations allowed) ----------------
__device__ __half g_xnh[MAXB * H];
__device__ float  g_q[MAXB * H];
__device__ float  g_vnew[MAXB * NKV * HD];
__device__ __half g_atth[MAXB * H];
__device__ float  g_rope[HD];
__device__ int    g_ticket;

#define DUAL_GRID 296

// ---------------- prep: zero scratch, compute rope, reset ticket ----------
__global__ void prep_kernel(int BH, int BGD, int L) {
    int i = blockIdx.x * 256 + threadIdx.x;
    if (i < BH)            g_q[i] = 0.f;
    else if (i < BH + BGD) g_vnew[i - BH] = 0.f;
    if (i == 0) g_ticket = DUAL_GRID;
    if (blockIdx.x == 0 && threadIdx.x < HD / 2) {
        int t = threadIdx.x;
        double freq = exp(-((double)t / (double)HD) * 13.122363377404329); // ln(5e5)
        double ang  = (double)L * freq;
        double cv = cos(ang), sv = sin(ang);
        g_rope[t]          = (float)(cv - sv);
        g_rope[t + HD / 2] = (float)(cv + sv);
    }
}

__global__ void zero_kernel(float* __restrict__ p, int n) {
    int i = blockIdx.x * 256 + threadIdx.x;
    if (i < n) p[i] = 0.f;
}

// ---------------- rmsnorm (writes fp16 xn) ----------------
__global__ void rmsnorm_kernel(const float* __restrict__ x, const float* __restrict__ w) {
    int b = blockIdx.x;
    const float* xr = x + (size_t)b * H;
    float ss = 0.f;
    for (int i = threadIdx.x; i < H; i += 256) { float v = xr[i]; ss += v * v; }
    __shared__ float red[256];
    red[threadIdx.x] = ss;
    __syncthreads();
    for (int o = 128; o > 0; o >>= 1) {
        if (threadIdx.x < o) red[threadIdx.x] += red[threadIdx.x + o];
        __syncthreads();
    }
    float inv = rsqrtf(red[0] * (1.f / H) + 1e-5f);
    for (int i = threadIdx.x; i < H; i += 256)
        g_xnh[(size_t)b * H + i] = __float2half(xr[i] * inv * w[i]);
}

// ---- fp16 GEMM: CTA 128x128, warp 64x32, m16n8k16, 64-K blocks ----
__device__ __forceinline__ void cpa16(void* dst, const void* src) {
    uint32_t d = (uint32_t)__cvta_generic_to_shared(dst);
    asm volatile("cp.async.cg.shared.global [%0], [%1], 16;" :: "r"(d), "l"(src));
}
__device__ __forceinline__ void redv2(float* p, float v0, float v1) {
    asm volatile("red.global.add.v2.f32 [%0], {%1, %2};" :: "l"(p), "f"(v0), "f"(v1) : "memory");
}
__device__ __forceinline__ uint32_t packh2(float lo, float hi) {
    uint32_t r;
    asm("cvt.rn.f16x2.f32 %0, %1, %2;" : "=r"(r) : "f"(hi), "f"(lo));
    return r;
}

// stage layout (64-K block per stage)
#define ASTRH   72                           // A row stride in halves (144B -> +4 banks/row)
#define A_BYTES (128 * ASTRH * 2)            // 18432
#define BSTR    140                          // B fp32 row stride in floats (disjoint banks)
#define B_OFF   A_BYTES
#define B_BYTES (64 * BSTR * 4)              // 35840
#define STGB    (A_BYTES + B_BYTES)          // 54272 per stage
#define GEMM_SMEM (2 * STGB)                 // 108544

// A: fp16 [M=128 rows][K halves]; B: fp32 [K][N]; C accumulated via red.v2.
// kchunk must be a multiple of 64.
__device__ __forceinline__ void gemm_core(
    const __half* __restrict__ A, const float* __restrict__ B, float* __restrict__ C,
    int K, int N, int n0, int kbeg, int kchunk, char* smc)
{
    int niter = kchunk / 64;
    int tid = threadIdx.x;
    int lane = tid & 31;
    int warp = tid >> 5;
    int mb = (warp >> 2) * 64;       // 2x4 warp grid over 128x128 tile
    int nb = (warp & 3) * 32;

    int lgrp = lane >> 3;
    int lrow = (lgrp & 1) * 8 + (lane & 7);
    int lcol = (lgrp >> 1) * 8;      // halves
    uint32_t smsh = (uint32_t)__cvta_generic_to_shared(smc);

    float c[4][4][4];
    #pragma unroll
    for (int i = 0; i < 4; i++)
        #pragma unroll
        for (int j = 0; j < 4; j++)
            #pragma unroll
            for (int k = 0; k < 4; k++) c[i][j][k] = 0.f;

    auto stage = [&](int buf, int k0) {
        char* base = smc + buf * STGB;
        // A: 128 rows x 64 halves (128B) -> 1024 x 16B
        #pragma unroll
        for (int j = 0; j < 4; j++) {
            int id = tid + 256 * j;
            int row = id >> 3, seg = id & 7;
            cpa16(base + row * (ASTRH * 2) + seg * 16,
                  A + (size_t)row * K + k0 + seg * 8);
        }
        // B: 64 k-rows x 128 fp32 (512B) -> 2048 x 16B
        #pragma unroll
        for (int j = 0; j < 8; j++) {
            int id = tid + 256 * j;
            int row = id >> 5, nq = (id & 31) * 4;
            cpa16(base + B_OFF + (row * BSTR + nq) * 4,
                  B + (size_t)(k0 + row) * N + n0 + nq);
        }
        asm volatile("cp.async.commit_group;");
    };

    stage(0, kbeg);
    for (int i = 0; i < niter; i++) {
        if (i + 1 < niter) {
            stage((i + 1) & 1, kbeg + (i + 1) * 64);
            asm volatile("cp.async.wait_group 1;");
        } else {
            asm volatile("cp.async.wait_group 0;");
        }
        __syncthreads();

        uint32_t Ash = smsh + (uint32_t)((i & 1) * STGB);
        const float* raw = (const float*)(smc + (i & 1) * STGB + B_OFF);
        #pragma unroll
        for (int ks = 0; ks < 4; ks++) {        // four k16 steps per 64-K block
            uint32_t a[4][4], bf[4][2];
            #pragma unroll
            for (int im = 0; im < 4; im++) {
                uint32_t adr = Ash + (uint32_t)((mb + im * 16 + lrow) * ASTRH
                                                + ks * 16 + lcol) * 2;
                asm volatile(
                    "ldmatrix.sync.aligned.m8n8.x4.shared.b16 {%0,%1,%2,%3}, [%4];"
                    : "=r"(a[im][0]), "=r"(a[im][1]), "=r"(a[im][2]), "=r"(a[im][3])
                    : "r"(adr));
            }
            #pragma unroll
            for (int jn = 0; jn < 4; jn++) {
                int n = nb + jn * 8 + (lane >> 2);
                int kq = ks * 16 + (lane & 3) * 2;
                bf[jn][0] = packh2(raw[kq * BSTR + n],       raw[(kq + 1) * BSTR + n]);
                bf[jn][1] = packh2(raw[(kq + 8) * BSTR + n], raw[(kq + 9) * BSTR + n]);
            }
            #pragma unroll
            for (int im = 0; im < 4; im++)
                #pragma unroll
                for (int jn = 0; jn < 4; jn++)
                    asm volatile(
                        "mma.sync.aligned.m16n8k16.row.col.f32.f16.f16.f32 "
                        "{%0,%1,%2,%3},{%4,%5,%6,%7},{%8,%9},{%0,%1,%2,%3};"
                        : "+f"(c[im][jn][0]), "+f"(c[im][jn][1]),
                          "+f"(c[im][jn][2]), "+f"(c[im][jn][3])
                        : "r"(a[im][0]), "r"(a[im][1]), "r"(a[im][2]), "r"(a[im][3]),
                          "r"(bf[jn][0]), "r"(bf[jn][1]));
        }
        __syncthreads();   // buffer fully consumed before it is restaged
    }

    #pragma unroll
    for (int im = 0; im < 4; im++) {
        int r = mb + im * 16 + (lane >> 2);
        #pragma unroll
        for (int jn = 0; jn < 4; jn++) {
            int col = n0 + nb + jn * 8 + (lane & 3) * 2;
            redv2(&C[(size_t)r * N + col],       c[im][jn][0], c[im][jn][1]);
            redv2(&C[(size_t)(r + 8) * N + col], c[im][jn][2], c[im][jn][3]);
        }
    }
    __syncthreads();   // smem safe before next persistent item stages
}

// persistent dual GEMM (wq + wv) with ticket work-stealing
#define DUAL_KS 16
__global__ void __launch_bounds__(256, 2) gemm_dual(
    const __half* __restrict__ A,
    const float* __restrict__ B1, float* __restrict__ C1, int N1, int nb1,
    const float* __restrict__ B2, float* __restrict__ C2, int N2, int K,
    int nbTotal)
{
    extern __shared__ char smc[];
    __shared__ int s_item;
    int kchunk = K / DUAL_KS;                 // 256 (4 x 64-K blocks)
    int nItems = nbTotal * DUAL_KS;           // 640
    int item = blockIdx.x;
    while (item < nItems) {
        int nb = item % nbTotal;
        int ks = item / nbTotal;
        if (nb < nb1) gemm_core(A, B1, C1, K, N1, nb * 128, ks * kchunk, kchunk, smc);
        else          gemm_core(A, B2, C2, K, N2, (nb - nb1) * 128, ks * kchunk, kchunk, smc);
        if (threadIdx.x == 0) s_item = atomicAdd(&g_ticket, 1);
        __syncthreads();
        item = s_item;
    }
}

__global__ void __launch_bounds__(256, 2) gemm_single(
    const __half* __restrict__ A, const float* __restrict__ B, float* __restrict__ C,
    int N, int K)
{
    extern __shared__ char smc[];
    int kchunk = K / gridDim.y;               // 512 (8 x 64-K blocks)
    gemm_core(A, B, C, K, N, blockIdx.x * 128, blockIdx.y * kchunk, kchunk, smc);
}

// ---------------- attention: persistent CTAs, warp-local softmax ----------
__global__ void __launch_bounds__(256, 4) attn_kernel(
    const float* __restrict__ Kc, const float* __restrict__ Vc, int L, int units)
{
    __shared__ float sc[NREP][SCP];
    __shared__ float pout[8][NREP][HD];
    __shared__ float wm[8][NREP], ws[8][NREP];
    __shared__ float fac[8][NREP], gsum[NREP];

    int t = threadIdx.x, lane = t & 31, w = t >> 5;
    bool hi16 = (lane & 16) != 0, hi8 = (lane & 8) != 0;
    float4 rp = *(const float4*)(g_rope + lane * 4);

    for (int bg = blockIdx.x; bg < units; bg += gridDim.x) {
        int b = bg >> 3, g = bg & 7;

        float4 q[NREP];
        #pragma unroll
        for (int r = 0; r < NREP; r++) {
            float4 qv = *(const float4*)(g_q + (size_t)b * H + (g * NREP + r) * HD + lane * 4);
            q[r].x = qv.x * rp.x * 0.08838834764831845f;
            q[r].y = qv.y * rp.y * 0.08838834764831845f;
            q[r].z = qv.z * rp.z * 0.08838834764831845f;
            q[r].w = qv.w * rp.w * 0.08838834764831845f;
        }

        const float* Kb = Kc + (size_t)bg * L * HD;
        int lbeg = w * (L >> 3);
        int lend = lbeg + (L >> 3);
        const float* kp = Kb + (size_t)lbeg * HD + lane * 4;
        float mloc = -1e30f;
        for (int l = lbeg; l < lend; l += 4, kp += 4 * HD) {
            float4 k0 = *(const float4*)kp;
            float4 k1 = *(const float4*)(kp + HD);
            float4 k2 = *(const float4*)(kp + 2 * HD);
            float4 k3 = *(const float4*)(kp + 3 * HD);

            #pragma unroll
            for (int pair = 0; pair < 2; pair++) {
                float4 ka = pair ? k2 : k0;
                float4 kb = pair ? k3 : k1;
                float p0[4], p1[4];
                #pragma unroll
                for (int r = 0; r < 4; r++) {
                    p0[r] = ka.x * q[r].x + ka.y * q[r].y + ka.z * q[r].z + ka.w * q[r].w;
                    p1[r] = kb.x * q[r].x + kb.y * q[r].y + kb.z * q[r].z + kb.w * q[r].w;
                }
                float a0 = hi16 ? p0[2] : p0[0];
                float a1 = hi16 ? p0[3] : p0[1];
                a0 += __shfl_xor_sync(0xffffffffu, hi16 ? p0[0] : p0[2], 16);
                a1 += __shfl_xor_sync(0xffffffffu, hi16 ? p0[1] : p0[3], 16);
                float c0 = hi8 ? a1 : a0;
                c0 += __shfl_xor_sync(0xffffffffu, hi8 ? a0 : a1, 8);
                c0 += __shfl_xor_sync(0xffffffffu, c0, 4);
                c0 += __shfl_xor_sync(0xffffffffu, c0, 2);
                c0 += __shfl_xor_sync(0xffffffffu, c0, 1);

                float b0 = hi16 ? p1[2] : p1[0];
                float b1 = hi16 ? p1[3] : p1[1];
                b0 += __shfl_xor_sync(0xffffffffu, hi16 ? p1[0] : p1[2], 16);
                b1 += __shfl_xor_sync(0xffffffffu, hi16 ? p1[1] : p1[3], 16);
                float c1 = hi8 ? b1 : b0;
                c1 += __shfl_xor_sync(0xffffffffu, hi8 ? b0 : b1, 8);
                c1 += __shfl_xor_sync(0xffffffffu, c1, 4);
                c1 += __shfl_xor_sync(0xffffffffu, c1, 2);
                c1 += __shfl_xor_sync(0xffffffffu, c1, 1);

                mloc = fmaxf(mloc, fmaxf(c0, c1));
                if ((lane & 7) == 0) {
                    int r = lane >> 3;
                    sc[r][l + pair * 2]     = c0;
                    sc[r][l + pair * 2 + 1] = c1;
                }
            }
        }
        __syncwarp();

        int r0i = lane >> 3, cix = lane & 7;
        float s_w = 0.f;
        int pcnt = L >> 6;
        for (int j = 0; j < pcnt; j++) {
            int l = lbeg + cix + j * 8;
            float p = __expf(sc[r0i][l] - mloc);
            sc[r0i][l] = p;
            s_w += p;
        }
        s_w += __shfl_xor_sync(0xffffffffu, s_w, 4);
        s_w += __shfl_xor_sync(0xffffffffu, s_w, 2);
        s_w += __shfl_xor_sync(0xffffffffu, s_w, 1);
        __syncwarp();

        const float* Vb = Vc + (size_t)bg * L * HD;
        const float* vp = Vb + (size_t)lbeg * HD + lane * 4;
        float4 o0 = {0,0,0,0}, o1 = o0, o2 = o0, o3 = o0;
        for (int l = lbeg; l < lend; l += 4, vp += 4 * HD) {
            float4 v0 = *(const float4*)vp;
            float4 v1 = *(const float4*)(vp + HD);
            float4 v2 = *(const float4*)(vp + 2 * HD);
            float4 v3 = *(const float4*)(vp + 3 * HD);
            float4 pa = *(const float4*)&sc[0][l];
            float4 pb = *(const float4*)&sc[1][l];
            float4 pc = *(const float4*)&sc[2][l];
            float4 pd = *(const float4*)&sc[3][l];
            o0.x += pa.x*v0.x + pa.y*v1.x + pa.z*v2.x + pa.w*v3.x;
            o0.y += pa.x*v0.y + pa.y*v1.y + pa.z*v2.y + pa.w*v3.y;
            o0.z += pa.x*v0.z + pa.y*v1.z + pa.z*v2.z + pa.w*v3.z;
            o0.w += pa.x*v0.w + pa.y*v1.w + pa.z*v2.w + pa.w*v3.w;
            o1.x += pb.x*v0.x + pb.y*v1.x + pb.z*v2.x + pb.w*v3.x;
            o1.y += pb.x*v0.y + pb.y*v1.y + pb.z*v2.y + pb.w*v3.y;
            o1.z += pb.x*v0.z + pb.y*v1.z + pb.z*v2.z + pb.w*v3.z;
            o1.w += pb.x*v0.w + pb.y*v1.w + pb.z*v2.w + pb.w*v3.w;
            o2.x += pc.x*v0.x + pc.y*v1.x + pc.z*v2.x + pc.w*v3.x;
            o2.y += pc.x*v0.y + pc.y*v1.y + pc.z*v2.y + pc.w*v3.y;
            o2.z += pc.x*v0.z + pc.y*v1.z + pc.z*v2.z + pc.w*v3.z;
            o2.w += pc.x*v0.w + pc.y*v1.w + pc.z*v2.w + pc.w*v3.w;
            o3.x += pd.x*v0.x + pd.y*v1.x + pd.z*v2.x + pd.w*v3.x;
            o3.y += pd.x*v0.y + pd.y*v1.y + pd.z*v2.y + pd.w*v3.y;
            o3.z += pd.x*v0.z + pd.y*v1.z + pd.z*v2.z + pd.w*v3.z;
            o3.w += pd.x*v0.w + pd.y*v1.w + pd.z*v2.w + pd.w*v3.w;
        }
        ((float4*)&pout[w][0][0])[lane] = o0;
        ((float4*)&pout[w][1][0])[lane] = o1;
        ((float4*)&pout[w][2][0])[lane] = o2;
        ((float4*)&pout[w][3][0])[lane] = o3;
        if ((lane & 7) == 0) {
            wm[w][r0i] = mloc;
            ws[w][r0i] = s_w;
        }
        __syncthreads();

        if (t < NREP) {
            float mg = -1e30f;
            #pragma unroll
            for (int ww = 0; ww < 8; ww++) mg = fmaxf(mg, wm[ww][t]);
            float sg = 0.f;
            #pragma unroll
            for (int ww = 0; ww < 8; ww++) {
                float f = __expf(wm[ww][t] - mg);
                fac[ww][t] = f;
                sg += ws[ww][t] * f;
            }
            gsum[t] = sg;
        }
        __syncthreads();

        // reduce, normalize, add v_new; store fp16 for the wo GEMM
        for (int i = t; i < NREP * HD; i += 256) {
            int rr = i >> 7, d = i & (HD - 1);
            float acc = 0.f;
            #pragma unroll
            for (int gg = 0; gg < 8; gg++) acc += pout[gg][rr][d] * fac[gg][rr];
            acc = acc / gsum[rr] + g_vnew[((size_t)b * NKV + g) * HD + d];
            g_atth[(size_t)b * H + (g * NREP + rr) * HD + d] = __float2half(acc);
        }
        __syncthreads();
    }
}

// ---------------- launch ----------------
extern "C" void kernel_launch(void* const* d_in, const int* in_sizes, int n_in,
                              void* d_out, int out_size)
{
    const float* x  = (const float*)d_in[0];
    const float* kc = (const float*)d_in[1];
    const float* vc = (const float*)d_in[2];
    const float* nw = (const float*)d_in[3];
    const float* wq = (const float*)d_in[4];
    // d_in[5] (wk) provably does not affect the output: softmax over a
    // length-1 axis is identically 1, so new_out == v_new.
    const float* wv = (const float*)d_in[6];
    const float* wo = (const float*)d_in[7];
    float* out = (float*)d_out;

    int B = in_sizes[0] / H;                 // 128
    int L = in_sizes[1] / (B * NKV * HD);    // 1024
    int BH = B * H, BGD = B * NKV * HD;
    int units = B * NKV;                     // 1024
    int agrid = (units % 2 == 0) ? units / 2 : units;

    __half *p_xnh, *p_atth;
    float *p_q, *p_vnew;
    cudaGetSymbolAddress((void**)&p_xnh,  g_xnh);
    cudaGetSymbolAddress((void**)&p_q,    g_q);
    cudaGetSymbolAddress((void**)&p_vnew, g_vnew);
    cudaGetSymbolAddress((void**)&p_atth, g_atth);

    cudaFuncSetAttribute(gemm_dual,   cudaFuncAttributeMaxDynamicSharedMemorySize, GEMM_SMEM);
    cudaFuncSetAttribute(gemm_single, cudaFuncAttributeMaxDynamicSharedMemorySize, GEMM_SMEM);

    int nbTotal = H / 128 + NKV * HD / 128;  // 32 + 8 = 40
    int zn = (BH + BGD + 255) / 256;
    prep_kernel<<<zn, 256>>>(BH, BGD, L);                                        // 0
    rmsnorm_kernel<<<B, 256>>>(x, nw);                                           // 1
    zero_kernel<<<(BH + 255) / 256, 256>>>(out, BH);                             // 2
    gemm_dual<<<DUAL_GRID, 256, GEMM_SMEM>>>(                                    // 3 <- profiled
        p_xnh, wq, p_q, H, H / 128, wv, p_vnew, NKV * HD, H, nbTotal);
    attn_kernel<<<agrid, 256>>>(kc, vc, L, units);                               // 4
    gemm_single<<<dim3(H / 128, 8), 256, GEMM_SMEM>>>(p_atth, wo, out, H, H);    // 5
}